// round 7
// baseline (speedup 1.0000x reference)
#include <cuda_runtime.h>

// FP_14396730376440 — fan-beam forward projection, geometry recomputed on-GPU.
// Zero-DRAM-stream in-kernel merge of two affine crossing sequences, software-
// pipelined: interval i's taps are loaded with an address computed during
// interval i-1, so F2I/IMAD/LDG latency overlaps the merge's carried chain.

#define ND 368
#define NV 180
#define NRAYS (ND * NV)
#define IMG_W 256
#define IMG_H 256
#define PAD 2
#define PW (IMG_W + 2 * PAD)     // 260
#define NCHUNK 8
#define F_INF __int_as_float(0x7f800000)

// ---------------- static device scratch ----------------
__device__ float2 d_img_pair[PW * PW];
__device__ float4 d_rayA[NRAYS];   // invx, offx, invy, offy
__device__ float4 d_rayB[NRAYS];   // fDx, fsx, fDy, fsy   (sample-pos affine)
__device__ float4 d_rayC[NRAYS];   // lo, hi, Dx, Dy
__device__ float  d_rayS[NRAYS];   // s2d

#define PAD_BLOCKS ((PW * PW + 255) / 256)
#define RAY_BLOCKS ((NRAYS + 255) / 256)

// ---------------- K1: fused pad + per-ray setup (pure f32) ----------------
__global__ void setup_kernel(const float* __restrict__ img)
{
    if (blockIdx.x < PAD_BLOCKS) {
        int idx = blockIdx.x * 256 + threadIdx.x;
        if (idx >= PW * PW) return;
        int y = idx / PW, x = idx % PW;
        int iy = y - PAD;
        auto px = [&](int xx) -> float {
            int ix = xx - PAD;
            if ((unsigned)ix < (unsigned)IMG_W && (unsigned)iy < (unsigned)IMG_H)
                return img[iy * IMG_W + ix];
            return 0.0f;
        };
        d_img_pair[idx] = make_float2(px(x), px(x + 1));
        return;
    }

    int q = (blockIdx.x - PAD_BLOCKS) * 256 + threadIdx.x;
    if (q >= NRAYS) return;
    int v = q / ND;
    int d = q - v * ND;

    float sb, cb;
    sincospif((float)v / 90.0f, &sb, &cb);        // beta = v * 2*pi/180
    float rdy = 2.0f * (float)d - 367.0f;
    float sx = -500.0f * cb, sy = 500.0f * sb;
    float Dx = fmaf(sb, rdy, 500.0f * cb) - sx;
    float Dy = fmaf(cb, rdy, -500.0f * sb) - sy;
    float cx = -128.0f - sx, cy = -128.0f - sy;
    float invx = 1.0f / Dx, invy = 1.0f / Dy;
    float offx = cx * invx, offy = cy * invy;

    // Window endpoints in the SAME fmaf form the merge loop uses.
    float ex0 = offx, ex1 = fmaf(256.0f, invx, offx);
    float ey0 = offy, ey1 = fmaf(256.0f, invy, offy);
    float lo = fmaxf(fmaxf(fminf(ex0, ex1), fminf(ey0, ey1)), 0.0f);
    float hi = fminf(fminf(fmaxf(ex0, ex1), fmaxf(ey0, ey1)), 1.0f);

    const float scale = 128.0f / 127.5f;
    d_rayA[q] = make_float4(invx, offx, invy, offy);
    d_rayB[q] = make_float4(Dx * scale, fmaf(sx, scale, 127.5f),
                            Dy * scale, fmaf(sy, scale, 127.5f));
    d_rayC[q] = make_float4(lo, hi, Dx, Dy);
    d_rayS[q] = sqrtf(fmaf(Dx, Dx, Dy * Dy));
}

// find first crossing (ascending order) with value >= clo
__device__ __forceinline__ void init_family(float clo, float Df, float inv,
                                            float off, float dirf,
                                            float& kf, float& val)
{
    float k = rintf((clo - off) * Df);
    k = fminf(fmaxf(k, -2.0f), 258.0f);
    #pragma unroll
    for (int i = 0; i < 4; ++i) {
        float vc = fmaf(k, inv, off);
        if (vc < clo)                                k += dirf;
        else if (fmaf(k - dirf, inv, off) >= clo)    k -= dirf;
        else break;
    }
    kf = k;
    val = fmaf(k, inv, off);
}

// ---------------- K2: main kernel, 8 chunk-threads per ray ----------------
__global__ __launch_bounds__(256)
void fp_kernel(float* __restrict__ out)
{
    const int g = blockIdx.x * blockDim.x + threadIdx.x;
    if (g >= NRAYS * NCHUNK) return;
    const int q = g >> 3;
    const int chunk = g & 7;

    const float4 A = d_rayA[q];
    const float4 B = d_rayB[q];
    const float4 C = d_rayC[q];
    const float invx = A.x, offx = A.y, invy = A.z, offy = A.w;
    const float fDx = B.x, fsx = B.y, fDy = B.z, fsy = B.w;
    const float lo = C.x, hi = C.y, Dx = C.z, Dy = C.w;
    const float dirx = (invx > 0.0f) ? 1.0f : -1.0f;
    const float diry = (invy > 0.0f) ? 1.0f : -1.0f;

    // chunk owns intervals starting in [clo, limit)
    const float w8 = (hi - lo) * 0.125f;
    const float clo = fmaf((float)chunk, w8, lo);
    const float limit = (chunk == 7) ? F_INF : fmaf((float)(chunk + 1), w8, lo);

    float kx, vx, ky, vy;
    init_family(clo, Dx, invx, offx, dirx, kx, vx);
    init_family(clo, Dy, invy, offy, diry, ky, vy);

    float cprev = fminf(vx, vy);
    if (vx <= vy) { kx += dirx; vx = fmaf(kx, invx, offx); }
    else          { ky += diry; vy = fmaf(ky, invy, offy); }

    const float2* __restrict__ ip = d_img_pair + (PAD * PW + PAD);

    // ---- pipeline pre-header: compute interval 0's params ----
    float nxt = fminf(vx, vy);
    bool have = (cprev < limit) && (nxt <= hi);

    float w_c   = nxt - cprev;
    float mid   = fmaf(0.5f, w_c, cprev);
    float ixp   = fmaf(mid, fDx, fsx);
    float iyp   = fmaf(mid, fDy, fsy);
    float x0f   = floorf(ixp);
    float y0f   = floorf(iyp);
    float fx_c  = ixp - x0f;
    float fy_c  = iyp - y0f;
    int   idx_c = __float2int_rn(y0f) * PW + __float2int_rn(x0f);

    if (vx <= vy) { kx += dirx; vx = fmaf(kx, invx, offx); }
    else          { ky += diry; vy = fmaf(ky, invy, offy); }
    cprev = nxt;

    float acc = 0.0f;

    #pragma unroll 1
    while (have) {
        // loads for CURRENT interval — address was ready last iteration
        const float2 t0 = __ldg(ip + idx_c);
        const float2 t1 = __ldg(ip + idx_c + PW);

        // compute NEXT interval (overlaps the loads above)
        const float nxt_n = fminf(vx, vy);
        const bool have_n = (cprev < limit) && (nxt_n <= hi);

        const float w_n   = nxt_n - cprev;
        const float mid_n = fmaf(0.5f, w_n, cprev);
        const float ix_n  = fmaf(mid_n, fDx, fsx);
        const float iy_n  = fmaf(mid_n, fDy, fsy);
        const float x0n   = floorf(ix_n);
        const float y0n   = floorf(iy_n);
        const float fx_n  = ix_n - x0n;
        const float fy_n  = iy_n - y0n;
        const int  idx_n  = __float2int_rn(y0n) * PW + __float2int_rn(x0n);

        if (vx <= vy) { kx += dirx; vx = fmaf(kx, invx, offx); }
        else          { ky += diry; vy = fmaf(ky, invy, offy); }
        cprev = nxt_n;

        // consume CURRENT interval
        const float top = fmaf(fx_c, t0.y - t0.x, t0.x);
        const float bot = fmaf(fx_c, t1.y - t1.x, t1.x);
        acc = fmaf(w_c, fmaf(fy_c, bot - top, top), acc);

        // rotate pipeline
        w_c = w_n; fx_c = fx_n; fy_c = fy_n; idx_c = idx_n;
        have = have_n;
    }

    // combine the 8 chunk partials (threads 8r..8r+7 share a warp)
    acc += __shfl_xor_sync(0xffffffffu, acc, 1);
    acc += __shfl_xor_sync(0xffffffffu, acc, 2);
    acc += __shfl_xor_sync(0xffffffffu, acc, 4);

    if (chunk == 0) {
        const int v = q / ND;
        const int d = q - v * ND;
        out[d * NV + v] = d_rayS[q] * acc;
    }
}

extern "C" void kernel_launch(void* const* d_in, const int* in_sizes, int n_in,
                              void* d_out, int out_size)
{
    const float* img = (const float*)d_in[0];
    float* out = (float*)d_out;

    setup_kernel<<<PAD_BLOCKS + RAY_BLOCKS, 256>>>(img);
    fp_kernel<<<(NRAYS * NCHUNK + 255) / 256, 256>>>(out);
}

// round 8
// speedup vs baseline: 1.1914x; 1.1914x over previous
#include <cuda_runtime.h>

// FP_14396730376440 — fan-beam forward projection, geometry recomputed on-GPU.
// In-kernel merge of two affine crossing sequences. R8: quad-packed image
// (one LDG.128 per bilinear) + warp = 32 adjacent detectors at the same chunk
// so taps within a warp are spatially compact (L1 wavefront reduction).

#define ND 368
#define NV 180
#define NRAYS (ND * NV)
#define IMG_W 256
#define IMG_H 256
#define PAD 2
#define PW (IMG_W + 2 * PAD)     // 260
#define NCHUNK 8
#define F_INF __int_as_float(0x7f800000)

// ---------------- static device scratch ----------------
__device__ float4 d_img_quad[PW * PW];   // (v00, v10, v01, v11) per cell
__device__ float4 d_rayA[NRAYS];   // invx, offx, invy, offy
__device__ float4 d_rayB[NRAYS];   // fDx, fsx, fDy, fsy   (sample-pos affine)
__device__ float4 d_rayC[NRAYS];   // lo, hi, Dx, Dy
__device__ float  d_rayS[NRAYS];   // s2d

#define PAD_BLOCKS ((PW * PW + 255) / 256)
#define RAY_BLOCKS ((NRAYS + 255) / 256)

// ---------------- K1: fused quad-pack + per-ray setup (pure f32) ----------------
__global__ void setup_kernel(const float* __restrict__ img)
{
    if (blockIdx.x < PAD_BLOCKS) {
        int idx = blockIdx.x * 256 + threadIdx.x;
        if (idx >= PW * PW) return;
        int y = idx / PW, x = idx % PW;
        auto px = [&](int xx, int yy) -> float {
            int ix = xx - PAD, iy = yy - PAD;
            if ((unsigned)ix < (unsigned)IMG_W && (unsigned)iy < (unsigned)IMG_H)
                return img[iy * IMG_W + ix];
            return 0.0f;
        };
        d_img_quad[idx] = make_float4(px(x, y), px(x + 1, y),
                                      px(x, y + 1), px(x + 1, y + 1));
        return;
    }

    int q = (blockIdx.x - PAD_BLOCKS) * 256 + threadIdx.x;
    if (q >= NRAYS) return;
    int v = q / ND;
    int d = q - v * ND;

    float sb, cb;
    sincospif((float)v / 90.0f, &sb, &cb);        // beta = v * 2*pi/180
    float rdy = 2.0f * (float)d - 367.0f;
    float sx = -500.0f * cb, sy = 500.0f * sb;
    float Dx = fmaf(sb, rdy, 500.0f * cb) - sx;
    float Dy = fmaf(cb, rdy, -500.0f * sb) - sy;
    float cx = -128.0f - sx, cy = -128.0f - sy;
    float invx = 1.0f / Dx, invy = 1.0f / Dy;
    float offx = cx * invx, offy = cy * invy;

    // Window endpoints in the SAME fmaf form the merge loop uses.
    float ex0 = offx, ex1 = fmaf(256.0f, invx, offx);
    float ey0 = offy, ey1 = fmaf(256.0f, invy, offy);
    float lo = fmaxf(fmaxf(fminf(ex0, ex1), fminf(ey0, ey1)), 0.0f);
    float hi = fminf(fminf(fmaxf(ex0, ex1), fmaxf(ey0, ey1)), 1.0f);

    const float scale = 128.0f / 127.5f;
    d_rayA[q] = make_float4(invx, offx, invy, offy);
    d_rayB[q] = make_float4(Dx * scale, fmaf(sx, scale, 127.5f),
                            Dy * scale, fmaf(sy, scale, 127.5f));
    d_rayC[q] = make_float4(lo, hi, Dx, Dy);
    d_rayS[q] = sqrtf(fmaf(Dx, Dx, Dy * Dy));
}

// find first crossing (ascending order) with value >= clo
__device__ __forceinline__ void init_family(float clo, float Df, float inv,
                                            float off, float dirf,
                                            float& kf, float& val)
{
    float k = rintf((clo - off) * Df);
    k = fminf(fmaxf(k, -2.0f), 258.0f);
    #pragma unroll
    for (int i = 0; i < 4; ++i) {
        float vc = fmaf(k, inv, off);
        if (vc < clo)                                k += dirf;
        else if (fmaf(k - dirf, inv, off) >= clo)    k -= dirf;
        else break;
    }
    kf = k;
    val = fmaf(k, inv, off);
}

// ---------------- K2: main kernel ----------------
// Block = 256 threads = 32 adjacent rays x 8 chunk-warps.
// warp w handles chunk w for rays q = blockIdx.x*32 + lane.
__global__ __launch_bounds__(256)
void fp_kernel(float* __restrict__ out)
{
    __shared__ float s_part[NCHUNK][32];

    const int lane  = threadIdx.x & 31;
    const int chunk = threadIdx.x >> 5;
    const int q     = blockIdx.x * 32 + lane;   // 2070 * 32 = NRAYS exactly

    const float4 A = d_rayA[q];
    const float4 B = d_rayB[q];
    const float4 C = d_rayC[q];
    const float invx = A.x, offx = A.y, invy = A.z, offy = A.w;
    const float fDx = B.x, fsx = B.y, fDy = B.z, fsy = B.w;
    const float lo = C.x, hi = C.y, Dx = C.z, Dy = C.w;
    const float dirx = (invx > 0.0f) ? 1.0f : -1.0f;
    const float diry = (invy > 0.0f) ? 1.0f : -1.0f;

    // chunk owns intervals starting in [clo, limit)
    const float w8 = (hi - lo) * 0.125f;
    const float clo = fmaf((float)chunk, w8, lo);
    const float limit = (chunk == 7) ? F_INF : fmaf((float)(chunk + 1), w8, lo);

    float kx, vx, ky, vy;
    init_family(clo, Dx, invx, offx, dirx, kx, vx);
    init_family(clo, Dy, invy, offy, diry, ky, vy);

    float acc = 0.0f;
    float cprev = fminf(vx, vy);
    if (vx <= vy) { kx += dirx; vx = fmaf(kx, invx, offx); }
    else          { ky += diry; vy = fmaf(ky, invy, offy); }

    const float4* __restrict__ ip = d_img_quad + (PAD * PW + PAD);

    #pragma unroll 1
    while (cprev < limit) {
        const float nxt = fminf(vx, vy);
        if (nxt > hi) break;

        const float w   = nxt - cprev;
        const float mid = fmaf(0.5f, w, cprev);
        const float ix  = fmaf(mid, fDx, fsx);
        const float iy  = fmaf(mid, fDy, fsy);
        const float x0f = floorf(ix);
        const float y0f = floorf(iy);
        const float fx  = ix - x0f;
        const float fy  = iy - y0f;
        const int idx   = __float2int_rn(y0f) * PW + __float2int_rn(x0f);

        const float4 t = __ldg(ip + idx);    // v00, v10, v01, v11
        const float top = fmaf(fx, t.y - t.x, t.x);
        const float bot = fmaf(fx, t.w - t.z, t.z);
        acc = fmaf(w, fmaf(fy, bot - top, top), acc);

        if (vx <= vy) { kx += dirx; vx = fmaf(kx, invx, offx); }
        else          { ky += diry; vy = fmaf(ky, invy, offy); }
        cprev = nxt;
    }

    // combine 8 chunk partials per ray through shared memory
    s_part[chunk][lane] = acc;
    __syncthreads();

    if (chunk == 0) {
        float total = 0.0f;
        #pragma unroll
        for (int c = 0; c < NCHUNK; ++c)
            total += s_part[c][lane];

        const int v = q / ND;
        const int d = q - v * ND;
        out[d * NV + v] = d_rayS[q] * total;
    }
}

extern "C" void kernel_launch(void* const* d_in, const int* in_sizes, int n_in,
                              void* d_out, int out_size)
{
    const float* img = (const float*)d_in[0];
    float* out = (float*)d_out;

    setup_kernel<<<PAD_BLOCKS + RAY_BLOCKS, 256>>>(img);
    fp_kernel<<<NRAYS / 32, 256>>>(out);
}

// round 9
// speedup vs baseline: 1.2360x; 1.0375x over previous
#include <cuda_runtime.h>
#include <cuda_fp16.h>

// FP_14396730376440 — fan-beam forward projection, geometry recomputed on-GPU.
// R9: image stored as fp16 quad cells (v00,v10,v01,v11 = 8 bytes) in a tiled
// layout (8x4 cells = one 128B line), making a warp's compact tap-arc touch
// ~4-8 cache lines regardless of orientation (was up to 32 for vertical arcs).

#define ND 368
#define NV 180
#define NRAYS (ND * NV)
#define IMG_W 256
#define IMG_H 256
#define PAD 2
#define GW 264                 // padded grid dim (multiple of 8 and 4)
#define TILES_X (GW / 8)       // 33
#define NCELLS (GW * GW)
#define NCHUNK 8
#define F_INF __int_as_float(0x7f800000)

// ---------------- static device scratch ----------------
// cell (cx,cy), cx=x0+PAD, cy=y0+PAD: uint2 = (half2(v00,v10), half2(v01,v11))
__device__ uint2  d_img_tile[NCELLS];
__device__ float4 d_rayA[NRAYS];   // invx, offx, invy, offy
__device__ float4 d_rayB[NRAYS];   // fDx, fsx, fDy, fsy   (sample-pos affine)
__device__ float4 d_rayC[NRAYS];   // lo, hi, Dx, Dy
__device__ float  d_rayS[NRAYS];   // s2d

#define PAD_BLOCKS ((NCELLS + 255) / 256)
#define RAY_BLOCKS ((NRAYS + 255) / 256)

__device__ __forceinline__ int tile_idx(int cx, int cy)
{
    // tile = (cx>>3, cy>>2); within-tile = (cx&7, cy&3); 32 cells per tile
    return (((cy >> 2) * TILES_X + (cx >> 3)) << 5) + ((cy & 3) << 3) + (cx & 7);
}

// ---------------- K1: fused tile-pack + per-ray setup (pure f32) ----------------
__global__ void setup_kernel(const float* __restrict__ img)
{
    if (blockIdx.x < PAD_BLOCKS) {
        int idx = blockIdx.x * 256 + threadIdx.x;
        if (idx >= NCELLS) return;
        int cy = idx / GW, cx = idx % GW;
        auto px = [&](int xx, int yy) -> float {
            int ix = xx - PAD, iy = yy - PAD;
            if ((unsigned)ix < (unsigned)IMG_W && (unsigned)iy < (unsigned)IMG_H)
                return img[iy * IMG_W + ix];
            return 0.0f;
        };
        __half2 t = __floats2half2_rn(px(cx, cy),     px(cx + 1, cy));
        __half2 b = __floats2half2_rn(px(cx, cy + 1), px(cx + 1, cy + 1));
        uint2 cell;
        cell.x = *reinterpret_cast<unsigned*>(&t);
        cell.y = *reinterpret_cast<unsigned*>(&b);
        d_img_tile[tile_idx(cx, cy)] = cell;
        return;
    }

    int q = (blockIdx.x - PAD_BLOCKS) * 256 + threadIdx.x;
    if (q >= NRAYS) return;
    int v = q / ND;
    int d = q - v * ND;

    float sb, cb;
    sincospif((float)v / 90.0f, &sb, &cb);        // beta = v * 2*pi/180
    float rdy = 2.0f * (float)d - 367.0f;
    float sx = -500.0f * cb, sy = 500.0f * sb;
    float Dx = fmaf(sb, rdy, 500.0f * cb) - sx;
    float Dy = fmaf(cb, rdy, -500.0f * sb) - sy;
    float cx = -128.0f - sx, cy = -128.0f - sy;
    float invx = 1.0f / Dx, invy = 1.0f / Dy;
    float offx = cx * invx, offy = cy * invy;

    // Window endpoints in the SAME fmaf form the merge loop uses.
    float ex0 = offx, ex1 = fmaf(256.0f, invx, offx);
    float ey0 = offy, ey1 = fmaf(256.0f, invy, offy);
    float lo = fmaxf(fmaxf(fminf(ex0, ex1), fminf(ey0, ey1)), 0.0f);
    float hi = fminf(fminf(fmaxf(ex0, ex1), fmaxf(ey0, ey1)), 1.0f);

    const float scale = 128.0f / 127.5f;
    d_rayA[q] = make_float4(invx, offx, invy, offy);
    d_rayB[q] = make_float4(Dx * scale, fmaf(sx, scale, 127.5f),
                            Dy * scale, fmaf(sy, scale, 127.5f));
    d_rayC[q] = make_float4(lo, hi, Dx, Dy);
    d_rayS[q] = sqrtf(fmaf(Dx, Dx, Dy * Dy));
}

// find first crossing (ascending order) with value >= clo
__device__ __forceinline__ void init_family(float clo, float Df, float inv,
                                            float off, float dirf,
                                            float& kf, float& val)
{
    float k = rintf((clo - off) * Df);
    k = fminf(fmaxf(k, -2.0f), 258.0f);
    #pragma unroll
    for (int i = 0; i < 4; ++i) {
        float vc = fmaf(k, inv, off);
        if (vc < clo)                                k += dirf;
        else if (fmaf(k - dirf, inv, off) >= clo)    k -= dirf;
        else break;
    }
    kf = k;
    val = fmaf(k, inv, off);
}

// ---------------- K2: main kernel ----------------
// Block = 256 threads = 32 adjacent rays x 8 chunk-warps.
__global__ __launch_bounds__(256)
void fp_kernel(float* __restrict__ out)
{
    __shared__ float s_part[NCHUNK][32];

    const int lane  = threadIdx.x & 31;
    const int chunk = threadIdx.x >> 5;
    const int q     = blockIdx.x * 32 + lane;   // 2070 * 32 = NRAYS exactly

    const float4 A = d_rayA[q];
    const float4 B = d_rayB[q];
    const float4 C = d_rayC[q];
    const float invx = A.x, offx = A.y, invy = A.z, offy = A.w;
    const float fDx = B.x, fsx = B.y, fDy = B.z, fsy = B.w;
    const float lo = C.x, hi = C.y, Dx = C.z, Dy = C.w;
    const float dirx = (invx > 0.0f) ? 1.0f : -1.0f;
    const float diry = (invy > 0.0f) ? 1.0f : -1.0f;

    // chunk owns intervals starting in [clo, limit)
    const float w8 = (hi - lo) * 0.125f;
    const float clo = fmaf((float)chunk, w8, lo);
    const float limit = (chunk == 7) ? F_INF : fmaf((float)(chunk + 1), w8, lo);

    float kx, vx, ky, vy;
    init_family(clo, Dx, invx, offx, dirx, kx, vx);
    init_family(clo, Dy, invy, offy, diry, ky, vy);

    float acc = 0.0f;
    float cprev = fminf(vx, vy);
    if (vx <= vy) { kx += dirx; vx = fmaf(kx, invx, offx); }
    else          { ky += diry; vy = fmaf(ky, invy, offy); }

    #pragma unroll 1
    while (cprev < limit) {
        const float nxt = fminf(vx, vy);
        if (nxt > hi) break;

        const float w   = nxt - cprev;
        const float mid = fmaf(0.5f, w, cprev);
        const float ix  = fmaf(mid, fDx, fsx);
        const float iy  = fmaf(mid, fDy, fsy);
        const float x0f = floorf(ix);
        const float y0f = floorf(iy);
        const float fx  = ix - x0f;
        const float fy  = iy - y0f;
        const int cxi   = __float2int_rn(x0f) + PAD;
        const int cyi   = __float2int_rn(y0f) + PAD;

        const uint2 cell = __ldg(&d_img_tile[tile_idx(cxi, cyi)]);
        const float2 t = __half22float2(*reinterpret_cast<const __half2*>(&cell.x));
        const float2 b = __half22float2(*reinterpret_cast<const __half2*>(&cell.y));
        const float top = fmaf(fx, t.y - t.x, t.x);
        const float bot = fmaf(fx, b.y - b.x, b.x);
        acc = fmaf(w, fmaf(fy, bot - top, top), acc);

        if (vx <= vy) { kx += dirx; vx = fmaf(kx, invx, offx); }
        else          { ky += diry; vy = fmaf(ky, invy, offy); }
        cprev = nxt;
    }

    // combine 8 chunk partials per ray through shared memory
    s_part[chunk][lane] = acc;
    __syncthreads();

    if (chunk == 0) {
        float total = 0.0f;
        #pragma unroll
        for (int c = 0; c < NCHUNK; ++c)
            total += s_part[c][lane];

        const int v = q / ND;
        const int d = q - v * ND;
        out[d * NV + v] = d_rayS[q] * total;
    }
}

extern "C" void kernel_launch(void* const* d_in, const int* in_sizes, int n_in,
                              void* d_out, int out_size)
{
    const float* img = (const float*)d_in[0];
    float* out = (float*)d_out;

    setup_kernel<<<PAD_BLOCKS + RAY_BLOCKS, 256>>>(img);
    fp_kernel<<<NRAYS / 32, 256>>>(out);
}

// round 10
// speedup vs baseline: 1.2369x; 1.0007x over previous
#include <cuda_runtime.h>
#include <cuda_fp16.h>

// FP_14396730376440 — fan-beam forward projection, geometry recomputed on-GPU.
// R9: image stored as fp16 quad cells (v00,v10,v01,v11 = 8 bytes) in a tiled
// layout (8x4 cells = one 128B line), making a warp's compact tap-arc touch
// ~4-8 cache lines regardless of orientation (was up to 32 for vertical arcs).

#define ND 368
#define NV 180
#define NRAYS (ND * NV)
#define IMG_W 256
#define IMG_H 256
#define PAD 2
#define GW 264                 // padded grid dim (multiple of 8 and 4)
#define TILES_X (GW / 8)       // 33
#define NCELLS (GW * GW)
#define NCHUNK 8
#define F_INF __int_as_float(0x7f800000)

// ---------------- static device scratch ----------------
// cell (cx,cy), cx=x0+PAD, cy=y0+PAD: uint2 = (half2(v00,v10), half2(v01,v11))
__device__ uint2  d_img_tile[NCELLS];
__device__ float4 d_rayA[NRAYS];   // invx, offx, invy, offy
__device__ float4 d_rayB[NRAYS];   // fDx, fsx, fDy, fsy   (sample-pos affine)
__device__ float4 d_rayC[NRAYS];   // lo, hi, Dx, Dy
__device__ float  d_rayS[NRAYS];   // s2d

#define PAD_BLOCKS ((NCELLS + 255) / 256)
#define RAY_BLOCKS ((NRAYS + 255) / 256)

__device__ __forceinline__ int tile_idx(int cx, int cy)
{
    // tile = (cx>>3, cy>>2); within-tile = (cx&7, cy&3); 32 cells per tile
    return (((cy >> 2) * TILES_X + (cx >> 3)) << 5) + ((cy & 3) << 3) + (cx & 7);
}

// ---------------- K1: fused tile-pack + per-ray setup (pure f32) ----------------
__global__ void setup_kernel(const float* __restrict__ img)
{
    if (blockIdx.x < PAD_BLOCKS) {
        int idx = blockIdx.x * 256 + threadIdx.x;
        if (idx >= NCELLS) return;
        int cy = idx / GW, cx = idx % GW;
        auto px = [&](int xx, int yy) -> float {
            int ix = xx - PAD, iy = yy - PAD;
            if ((unsigned)ix < (unsigned)IMG_W && (unsigned)iy < (unsigned)IMG_H)
                return img[iy * IMG_W + ix];
            return 0.0f;
        };
        __half2 t = __floats2half2_rn(px(cx, cy),     px(cx + 1, cy));
        __half2 b = __floats2half2_rn(px(cx, cy + 1), px(cx + 1, cy + 1));
        uint2 cell;
        cell.x = *reinterpret_cast<unsigned*>(&t);
        cell.y = *reinterpret_cast<unsigned*>(&b);
        d_img_tile[tile_idx(cx, cy)] = cell;
        return;
    }

    int q = (blockIdx.x - PAD_BLOCKS) * 256 + threadIdx.x;
    if (q >= NRAYS) return;
    int v = q / ND;
    int d = q - v * ND;

    float sb, cb;
    sincospif((float)v / 90.0f, &sb, &cb);        // beta = v * 2*pi/180
    float rdy = 2.0f * (float)d - 367.0f;
    float sx = -500.0f * cb, sy = 500.0f * sb;
    float Dx = fmaf(sb, rdy, 500.0f * cb) - sx;
    float Dy = fmaf(cb, rdy, -500.0f * sb) - sy;
    float cx = -128.0f - sx, cy = -128.0f - sy;
    float invx = 1.0f / Dx, invy = 1.0f / Dy;
    float offx = cx * invx, offy = cy * invy;

    // Window endpoints in the SAME fmaf form the merge loop uses.
    float ex0 = offx, ex1 = fmaf(256.0f, invx, offx);
    float ey0 = offy, ey1 = fmaf(256.0f, invy, offy);
    float lo = fmaxf(fmaxf(fminf(ex0, ex1), fminf(ey0, ey1)), 0.0f);
    float hi = fminf(fminf(fmaxf(ex0, ex1), fmaxf(ey0, ey1)), 1.0f);

    const float scale = 128.0f / 127.5f;
    d_rayA[q] = make_float4(invx, offx, invy, offy);
    d_rayB[q] = make_float4(Dx * scale, fmaf(sx, scale, 127.5f),
                            Dy * scale, fmaf(sy, scale, 127.5f));
    d_rayC[q] = make_float4(lo, hi, Dx, Dy);
    d_rayS[q] = sqrtf(fmaf(Dx, Dx, Dy * Dy));
}

// find first crossing (ascending order) with value >= clo
__device__ __forceinline__ void init_family(float clo, float Df, float inv,
                                            float off, float dirf,
                                            float& kf, float& val)
{
    float k = rintf((clo - off) * Df);
    k = fminf(fmaxf(k, -2.0f), 258.0f);
    #pragma unroll
    for (int i = 0; i < 4; ++i) {
        float vc = fmaf(k, inv, off);
        if (vc < clo)                                k += dirf;
        else if (fmaf(k - dirf, inv, off) >= clo)    k -= dirf;
        else break;
    }
    kf = k;
    val = fmaf(k, inv, off);
}

// ---------------- K2: main kernel ----------------
// Block = 256 threads = 32 adjacent rays x 8 chunk-warps.
__global__ __launch_bounds__(256)
void fp_kernel(float* __restrict__ out)
{
    __shared__ float s_part[NCHUNK][32];

    const int lane  = threadIdx.x & 31;
    const int chunk = threadIdx.x >> 5;
    const int q     = blockIdx.x * 32 + lane;   // 2070 * 32 = NRAYS exactly

    const float4 A = d_rayA[q];
    const float4 B = d_rayB[q];
    const float4 C = d_rayC[q];
    const float invx = A.x, offx = A.y, invy = A.z, offy = A.w;
    const float fDx = B.x, fsx = B.y, fDy = B.z, fsy = B.w;
    const float lo = C.x, hi = C.y, Dx = C.z, Dy = C.w;
    const float dirx = (invx > 0.0f) ? 1.0f : -1.0f;
    const float diry = (invy > 0.0f) ? 1.0f : -1.0f;

    // chunk owns intervals starting in [clo, limit)
    const float w8 = (hi - lo) * 0.125f;
    const float clo = fmaf((float)chunk, w8, lo);
    const float limit = (chunk == 7) ? F_INF : fmaf((float)(chunk + 1), w8, lo);

    float kx, vx, ky, vy;
    init_family(clo, Dx, invx, offx, dirx, kx, vx);
    init_family(clo, Dy, invy, offy, diry, ky, vy);

    float acc = 0.0f;
    float cprev = fminf(vx, vy);
    if (vx <= vy) { kx += dirx; vx = fmaf(kx, invx, offx); }
    else          { ky += diry; vy = fmaf(ky, invy, offy); }

    #pragma unroll 1
    while (cprev < limit) {
        const float nxt = fminf(vx, vy);
        if (nxt > hi) break;

        const float w   = nxt - cprev;
        const float mid = fmaf(0.5f, w, cprev);
        const float ix  = fmaf(mid, fDx, fsx);
        const float iy  = fmaf(mid, fDy, fsy);
        const float x0f = floorf(ix);
        const float y0f = floorf(iy);
        const float fx  = ix - x0f;
        const float fy  = iy - y0f;
        const int cxi   = __float2int_rn(x0f) + PAD;
        const int cyi   = __float2int_rn(y0f) + PAD;

        const uint2 cell = __ldg(&d_img_tile[tile_idx(cxi, cyi)]);
        const float2 t = __half22float2(*reinterpret_cast<const __half2*>(&cell.x));
        const float2 b = __half22float2(*reinterpret_cast<const __half2*>(&cell.y));
        const float top = fmaf(fx, t.y - t.x, t.x);
        const float bot = fmaf(fx, b.y - b.x, b.x);
        acc = fmaf(w, fmaf(fy, bot - top, top), acc);

        if (vx <= vy) { kx += dirx; vx = fmaf(kx, invx, offx); }
        else          { ky += diry; vy = fmaf(ky, invy, offy); }
        cprev = nxt;
    }

    // combine 8 chunk partials per ray through shared memory
    s_part[chunk][lane] = acc;
    __syncthreads();

    if (chunk == 0) {
        float total = 0.0f;
        #pragma unroll
        for (int c = 0; c < NCHUNK; ++c)
            total += s_part[c][lane];

        const int v = q / ND;
        const int d = q - v * ND;
        out[d * NV + v] = d_rayS[q] * total;
    }
}

extern "C" void kernel_launch(void* const* d_in, const int* in_sizes, int n_in,
                              void* d_out, int out_size)
{
    const float* img = (const float*)d_in[0];
    float* out = (float*)d_out;

    setup_kernel<<<PAD_BLOCKS + RAY_BLOCKS, 256>>>(img);
    fp_kernel<<<NRAYS / 32, 256>>>(out);
}